// round 4
// baseline (speedup 1.0000x reference)
#include <cuda_runtime.h>
#include <cuda_bf16.h>
#include <mma.h>
#include <math.h>
#include <stdint.h>

using namespace nvcuda;

// Shapes fixed by the problem instance.
constexpr int kB  = 16;            // objects
constexpr int kP  = 4096;          // points per object
constexpr int kM  = 32;            // masks per object
constexpr int kD  = 768;           // feature dim
constexpr int kN  = kB * kM;       // 512 total masks

// Segsum tiling: CTA = (96 d-cols, object). 6 warps x 16 cols. One wave (128 CTAs).
constexpr int DC   = 96;           // d-cols per CTA
constexpr int NDCC = kD / DC;      // 8
constexpr int KT   = 16;           // points per K tile
constexpr int NIT  = kP / KT;      // 256
constexpr int BPAD = 104;          // padded bf16 stride for B tiles

// Scratch (device globals; no allocation allowed).
__device__ unsigned g_bits[kB * kP];     // packed mask bits per (b, p)
__device__ float g_npts[kN];
__device__ float g_avg[kN * kD];
__device__ float g_logits[kN * kN];
__device__ float g_tloss[kN];
__device__ float g_ploss[kN];

// ---------------------------------------------------------------------------
// zero npts accumulator
// ---------------------------------------------------------------------------
__global__ void zero_kernel() { g_npts[threadIdx.x] = 0.f; }

// ---------------------------------------------------------------------------
// Pack mask_pts [b][m][p] into one uint32 bitmask per (b, p), and accumulate
// npts via warp ballots (exact small-integer float atomics -> deterministic).
// ---------------------------------------------------------------------------
__global__ void pack_kernel(const float* __restrict__ mp) {
    const int b = blockIdx.y;
    const int p = blockIdx.x * blockDim.x + threadIdx.x;
    const int lane = threadIdx.x & 31;
    unsigned bm = 0;
#pragma unroll
    for (int m = 0; m < kM; ++m) {
        float v = mp[((size_t)(b * kM + m)) * kP + p];
        bm |= (v > 0.5f) ? (1u << m) : 0u;
    }
    g_bits[b * kP + p] = bm;
    unsigned cmine = 0;
#pragma unroll
    for (int m = 0; m < kM; ++m) {
        unsigned bal = __ballot_sync(0xffffffffu, (bm >> m) & 1u);
        if (lane == m) cmine = __popc(bal);
    }
    atomicAdd(&g_npts[b * kM + lane], (float)cmine);
}

// ---------------------------------------------------------------------------
// Segmented sum via wmma bf16 hi/lo GEMM; avg fused into epilogue.
// Per CTA (dc, b): out[32, 96] = mask[32, 4096] @ net_out_b[4096, 96]
//   A = mask bits as bf16 {0,1}; B = net_out fp32 split into bf16 hi + lo.
//   D += A@Bhi + A@Blo  (error ~2^-16, well inside 1e-3 tolerance).
// Double-buffered smem (1 sync/tile) + 2-tile register prefetch.
// ---------------------------------------------------------------------------
__global__ __launch_bounds__(192) void segsum_mma(const float* __restrict__ net_out) {
    __shared__ __align__(16) __nv_bfloat16 sA[2][kM][16];
    __shared__ __align__(16) __nv_bfloat16 sBh[2][KT][BPAD];
    __shared__ __align__(16) __nv_bfloat16 sBl[2][KT][BPAD];
    __shared__ __align__(16) float sOut[kM][DC];

    const int tid = threadIdx.x;
    const int w = tid >> 5;                    // warp 0..5
    const int dc = blockIdx.x, b = blockIdx.y;
    const float4* __restrict__ net4 =
        (const float4*)net_out + (size_t)b * kP * (kD / 4) + dc * (DC / 4);
    const unsigned* __restrict__ bitsb = g_bits + b * kP;

    wmma::fragment<wmma::accumulator, 16, 16, 16, float> acc0, acc1;
    wmma::fill_fragment(acc0, 0.f);
    wmma::fill_fragment(acc1, 0.f);

    float4 vb[2][2];   // B prefetch slots
    uint4  va[2];      // A (bits) prefetch slots
    const int am = tid >> 2;          // mask row (tid < 128)
    const int ak = (tid & 3) * 4;     // k quad

    auto LOAD = [&](int it, int slot) {
        const int p0 = it * KT;
#pragma unroll
        for (int j = 0; j < 2; ++j) {
            int idx = tid + j * 192;               // 384 float4 per tile
            int r = idx / 24, c4 = idx % 24;       // 16 rows x 24 float4
            vb[slot][j] = net4[(size_t)(p0 + r) * (kD / 4) + c4];
        }
        if (tid < 128) va[slot] = *(const uint4*)&bitsb[p0 + ak];
    };
    auto STS = [&](int slot, int buf) {
#pragma unroll
        for (int j = 0; j < 2; ++j) {
            int idx = tid + j * 192;
            int r = idx / 24, c4 = idx % 24;
            float4 v = vb[slot][j];
            uint32_t h01, h23, l01, l23;
            asm("cvt.rn.bf16x2.f32 %0, %1, %2;" : "=r"(h01) : "f"(v.y), "f"(v.x));
            asm("cvt.rn.bf16x2.f32 %0, %1, %2;" : "=r"(h23) : "f"(v.w), "f"(v.z));
            float bx = __uint_as_float(h01 << 16);
            float by = __uint_as_float(h01 & 0xFFFF0000u);
            float bz = __uint_as_float(h23 << 16);
            float bw = __uint_as_float(h23 & 0xFFFF0000u);
            asm("cvt.rn.bf16x2.f32 %0, %1, %2;" : "=r"(l01) : "f"(v.y - by), "f"(v.x - bx));
            asm("cvt.rn.bf16x2.f32 %0, %1, %2;" : "=r"(l23) : "f"(v.w - bw), "f"(v.z - bz));
            *(uint2*)&sBh[buf][r][c4 * 4] = make_uint2(h01, h23);
            *(uint2*)&sBl[buf][r][c4 * 4] = make_uint2(l01, l23);
        }
        if (tid < 128) {
            uint4 wv = va[slot];
            uint32_t p01 = (((wv.x >> am) & 1u) ? 0x3F80u : 0u) |
                           (((wv.y >> am) & 1u) ? 0x3F800000u : 0u);
            uint32_t p23 = (((wv.z >> am) & 1u) ? 0x3F80u : 0u) |
                           (((wv.w >> am) & 1u) ? 0x3F800000u : 0u);
            *(uint2*)&sA[buf][am][ak] = make_uint2(p01, p23);
        }
    };

    LOAD(0, 0);
    LOAD(1, 1);
    STS(0, 0);
    __syncthreads();

    const int nw = w * 16;
    for (int it = 0; it < NIT; ++it) {
        const int buf = it & 1;
        if (it + 2 < NIT) LOAD(it + 2, it & 1);

        wmma::fragment<wmma::matrix_a, 16, 16, 16, __nv_bfloat16, wmma::row_major> a0, a1;
        wmma::fragment<wmma::matrix_b, 16, 16, 16, __nv_bfloat16, wmma::row_major> bh, bl;
        wmma::load_matrix_sync(a0, &sA[buf][0][0], 16);
        wmma::load_matrix_sync(a1, &sA[buf][16][0], 16);
        wmma::load_matrix_sync(bh, &sBh[buf][0][nw], BPAD);
        wmma::load_matrix_sync(bl, &sBl[buf][0][nw], BPAD);
        wmma::mma_sync(acc0, a0, bh, acc0);
        wmma::mma_sync(acc0, a0, bl, acc0);
        wmma::mma_sync(acc1, a1, bh, acc1);
        wmma::mma_sync(acc1, a1, bl, acc1);

        if (it + 1 < NIT) STS((it + 1) & 1, (it + 1) & 1);
        __syncthreads();
    }

    wmma::store_matrix_sync(&sOut[0][nw], acc0, DC, wmma::mem_row_major);
    wmma::store_matrix_sync(&sOut[16][nw], acc1, DC, wmma::mem_row_major);
    __syncthreads();
#pragma unroll
    for (int j = 0; j < 16; ++j) {
        int idx = tid + j * 192;                 // 3072 outputs
        int m = idx / DC, c = idx % DC;
        float inv = 1.f / (g_npts[b * kM + m] + 1e-12f);
        g_avg[(size_t)(b * kM + m) * kD + dc * DC + c] = sOut[m][c] * inv;
    }
}

// ---------------------------------------------------------------------------
// logits[i,j] = scale * <mask_embs[i,:], avg[j,:]>   (512x512x768 fp32 GEMM)
// 32x64 tile per block, grid (8, 16) = 128 blocks (one wave), 2x4 per thread.
// ---------------------------------------------------------------------------
__global__ __launch_bounds__(256) void logits_kernel(const float* __restrict__ A,
                                                     const float* __restrict__ lscale) {
    __shared__ float As[16][36];   // [k][row], padded pitch
    __shared__ float Bs[16][68];
    const int bi = blockIdx.y, bj = blockIdx.x;
    const int tid = threadIdx.x;
    const int ti = tid >> 4, tj = tid & 15;     // 16x16 thread tile
    const int lr = tid >> 2;                    // load row
    const int lc = (tid & 3) * 4;               // load col quad
    float acc[2][4] = {};

    for (int k0 = 0; k0 < kD; k0 += 16) {
        float4 av = make_float4(0.f, 0.f, 0.f, 0.f);
        if (tid < 128)
            av = *(const float4*)&A[(size_t)(bi * 32 + lr) * kD + k0 + lc];
        float4 bv = *(const float4*)&g_avg[(size_t)(bj * 64 + lr) * kD + k0 + lc];
        __syncthreads();
        if (tid < 128) {
            As[lc + 0][lr] = av.x; As[lc + 1][lr] = av.y;
            As[lc + 2][lr] = av.z; As[lc + 3][lr] = av.w;
        }
        Bs[lc + 0][lr] = bv.x; Bs[lc + 1][lr] = bv.y;
        Bs[lc + 2][lr] = bv.z; Bs[lc + 3][lr] = bv.w;
        __syncthreads();
#pragma unroll
        for (int k = 0; k < 16; ++k) {
            float2 a = *(const float2*)&As[k][ti * 2];
            float4 bq = *(const float4*)&Bs[k][tj * 4];
            acc[0][0] += a.x * bq.x; acc[0][1] += a.x * bq.y;
            acc[0][2] += a.x * bq.z; acc[0][3] += a.x * bq.w;
            acc[1][0] += a.y * bq.x; acc[1][1] += a.y * bq.y;
            acc[1][2] += a.y * bq.z; acc[1][3] += a.y * bq.w;
        }
    }
    const float scale = expf(lscale[0]);
    const int i0 = bi * 32 + ti * 2, j0 = bj * 64 + tj * 4;
#pragma unroll
    for (int r = 0; r < 2; ++r) {
        float4 o;
        o.x = acc[r][0] * scale; o.y = acc[r][1] * scale;
        o.z = acc[r][2] * scale; o.w = acc[r][3] * scale;
        *(float4*)&g_logits[(size_t)(i0 + r) * kN + j0] = o;
    }
}

// ---------------------------------------------------------------------------
// Per-index i: texts_loss = LSE(row i) - diag; pts_loss = LSE(col i) - diag.
// ---------------------------------------------------------------------------
__global__ __launch_bounds__(128) void loss_kernel() {
    const int i = blockIdx.x;
    const int t = threadIdx.x;
    __shared__ float sr[128], sc[128];

    float rmax = -3.0e38f, cmax = -3.0e38f;
    for (int j = t; j < kN; j += 128) {
        rmax = fmaxf(rmax, g_logits[(size_t)i * kN + j]);
        cmax = fmaxf(cmax, g_logits[(size_t)j * kN + i]);
    }
    sr[t] = rmax; sc[t] = cmax;
    __syncthreads();
    for (int w = 64; w > 0; w >>= 1) {
        if (t < w) { sr[t] = fmaxf(sr[t], sr[t + w]); sc[t] = fmaxf(sc[t], sc[t + w]); }
        __syncthreads();
    }
    rmax = sr[0]; cmax = sc[0];
    __syncthreads();

    float rs = 0.f, cs = 0.f;
    for (int j = t; j < kN; j += 128) {
        rs += expf(g_logits[(size_t)i * kN + j] - rmax);
        cs += expf(g_logits[(size_t)j * kN + i] - cmax);
    }
    sr[t] = rs; sc[t] = cs;
    __syncthreads();
    for (int w = 64; w > 0; w >>= 1) {
        if (t < w) { sr[t] += sr[t + w]; sc[t] += sc[t + w]; }
        __syncthreads();
    }
    if (t == 0) {
        float diag = g_logits[(size_t)i * kN + i];
        bool valid = g_npts[i] > 0.f;
        g_tloss[i] = valid ? (rmax + logf(sr[0]) - diag) : 0.f;
        g_ploss[i] = valid ? (cmax + logf(sc[0]) - diag) : 0.f;
    }
}

// ---------------------------------------------------------------------------
// Final: nonzero-mean of both loss vectors, averaged.
// ---------------------------------------------------------------------------
__global__ void final_kernel(float* __restrict__ out) {
    const int t = threadIdx.x;   // 512 threads
    __shared__ float s_ts[512], s_tc[512], s_ps[512], s_pc[512];
    float tl = g_tloss[t], pl = g_ploss[t];
    s_ts[t] = (tl > 0.f) ? tl : 0.f;
    s_tc[t] = (tl > 0.f) ? 1.f : 0.f;
    s_ps[t] = (pl > 0.f) ? pl : 0.f;
    s_pc[t] = (pl > 0.f) ? 1.f : 0.f;
    __syncthreads();
    for (int w = 256; w > 0; w >>= 1) {
        if (t < w) {
            s_ts[t] += s_ts[t + w]; s_tc[t] += s_tc[t + w];
            s_ps[t] += s_ps[t + w]; s_pc[t] += s_pc[t + w];
        }
        __syncthreads();
    }
    if (t == 0) {
        float tm = (s_tc[0] > 0.f) ? s_ts[0] / s_tc[0] : 0.f;
        float pm = (s_pc[0] > 0.f) ? s_ps[0] / s_pc[0] : 0.f;
        out[0] = 0.5f * (tm + pm);
    }
}

// ---------------------------------------------------------------------------
// Launch. Inputs: net_out, pt_offset, mask_embs, mask_pts, logit_scale.
// pt_offset encodes the regular b*P layout (fixed shapes) -> not read.
// ---------------------------------------------------------------------------
extern "C" void kernel_launch(void* const* d_in, const int* in_sizes, int n_in,
                              void* d_out, int out_size) {
    (void)in_sizes; (void)n_in; (void)out_size;
    const float* net_out   = (const float*)d_in[0];
    const float* mask_embs = (const float*)d_in[2];
    const float* mask_pts  = (const float*)d_in[3];
    const float* lscale    = (const float*)d_in[4];

    zero_kernel<<<1, kN>>>();
    pack_kernel<<<dim3(kP / 256, kB), 256>>>(mask_pts);
    segsum_mma<<<dim3(NDCC, kB), 192>>>(net_out);
    logits_kernel<<<dim3(8, 16), 256>>>(mask_embs, lscale);
    loss_kernel<<<kN, 128>>>();
    final_kernel<<<1, kN>>>((float*)d_out);
}

// round 5
// speedup vs baseline: 1.6162x; 1.6162x over previous
#include <cuda_runtime.h>
#include <mma.h>
#include <math.h>
#include <stdint.h>

using namespace nvcuda;

// Shapes fixed by the problem instance.
constexpr int kB  = 16;            // objects
constexpr int kP  = 4096;          // points per object
constexpr int kM  = 32;            // masks per object
constexpr int kD  = 768;           // feature dim
constexpr int kN  = kB * kM;       // 512 total masks

// Segsum tiling: CTA = (96 d-cols, object), 6 warps, K-tile = 32 points.
constexpr int DC   = 96;
constexpr int NDCC = kD / DC;      // 8  -> grid 8x16 = 128 CTAs (one wave)
constexpr int KT   = 32;
constexpr int NIT  = kP / KT;      // 128

// Dynamic smem layout for segsum (bytes):
constexpr int SEG_B_STAGE = 32 * 100 * 4;              // 12800 per stage
constexpr int SEG_A_OFF   = 3 * SEG_B_STAGE;           // 38400
constexpr int SEG_A_STAGE = 32 * 40 * 4;               // 5120 per stage
constexpr int SEG_SMEM    = SEG_A_OFF + 3 * SEG_A_STAGE; // 53760

// Scratch (device globals; no allocation allowed).
__device__ unsigned g_bits[kB * kP];     // packed mask bits per (b, p)
__device__ float g_npts[kN];
__device__ float g_avg[kN * kD];
__device__ float g_logits[kN * kN];
__device__ float g_logitsT[kN * kN];
__device__ float g_tloss[kN];
__device__ float g_ploss[kN];

__device__ __forceinline__ void cpa16(uint32_t dst, const void* src) {
    asm volatile("cp.async.ca.shared.global [%0], [%1], 16;" :: "r"(dst), "l"(src));
}
#define CP_COMMIT() asm volatile("cp.async.commit_group;")

// ---------------------------------------------------------------------------
// zero npts accumulator
// ---------------------------------------------------------------------------
__global__ void zero_kernel() { g_npts[threadIdx.x] = 0.f; }

// ---------------------------------------------------------------------------
// Pack mask_pts [b][m][p] into one uint32 bitmask per (b, p), and accumulate
// npts via warp ballots (exact small-integer float atomics -> deterministic).
// ---------------------------------------------------------------------------
__global__ void pack_kernel(const float* __restrict__ mp) {
    const int b = blockIdx.y;
    const int p = blockIdx.x * blockDim.x + threadIdx.x;
    const int lane = threadIdx.x & 31;
    unsigned bm = 0;
#pragma unroll
    for (int m = 0; m < kM; ++m) {
        float v = mp[((size_t)(b * kM + m)) * kP + p];
        bm |= (v > 0.5f) ? (1u << m) : 0u;
    }
    g_bits[b * kP + p] = bm;
    unsigned cmine = 0;
#pragma unroll
    for (int m = 0; m < kM; ++m) {
        unsigned bal = __ballot_sync(0xffffffffu, (bm >> m) & 1u);
        if (lane == m) cmine = __popc(bal);
    }
    atomicAdd(&g_npts[b * kM + lane], (float)cmine);
}

// ---------------------------------------------------------------------------
// Segmented sum via tf32 wmma; avg fused into epilogue.
// Per CTA (dc, b): out[32, 96] = mask[32, 4096] @ net_out_b[4096, 96]
// A = mask bits as fp32 {0,1} (exact in tf32); B = net_out fp32 (tf32-rounded).
// 3-stage cp.async pipeline, K-tile = 32 (4 wmma k-steps), 6 warps x 16 cols.
// ---------------------------------------------------------------------------
__global__ __launch_bounds__(192) void segsum_mma(const float* __restrict__ net_out) {
    extern __shared__ char smc[];
    float* fB = (float*)smc;                  // 3 stages of [32][100]
    float* fA = (float*)(smc + SEG_A_OFF);    // 3 stages of [32][40]
    const uint32_t smbase = (uint32_t)__cvta_generic_to_shared(smc);
    const int tid = threadIdx.x, w = tid >> 5;
    const int dc = blockIdx.x, b = blockIdx.y;
    const float4* __restrict__ net4 =
        (const float4*)net_out + (size_t)b * kP * (kD / 4) + dc * (DC / 4);
    const unsigned* __restrict__ bitsb = g_bits + b * kP;

    auto ISSUE = [&](int it) {
        const int stage = it % 3;
        const int p0 = it * KT;
        const uint32_t bbase = smbase + stage * SEG_B_STAGE;
#pragma unroll
        for (int j = 0; j < 4; ++j) {          // 768 16B chunks, 4 per thread
            int c = tid + j * 192;
            int r = c / 24, c16 = c % 24;
            cpa16(bbase + (uint32_t)(r * 100 + c16 * 4) * 4,
                  net4 + (size_t)(p0 + r) * (kD / 4) + c16);
        }
        if (tid < 128) {                       // A tile: 32 masks x 32 k, fp32 0/1
            int am = tid >> 2, k0 = (tid & 3) * 8;
            uint4 w0 = *(const uint4*)&bitsb[p0 + k0];
            uint4 w1 = *(const uint4*)&bitsb[p0 + k0 + 4];
            float* dst = fA + stage * (32 * 40) + am * 40 + k0;
            *(float4*)dst = make_float4((float)((w0.x >> am) & 1), (float)((w0.y >> am) & 1),
                                        (float)((w0.z >> am) & 1), (float)((w0.w >> am) & 1));
            *(float4*)(dst + 4) = make_float4((float)((w1.x >> am) & 1), (float)((w1.y >> am) & 1),
                                              (float)((w1.z >> am) & 1), (float)((w1.w >> am) & 1));
        }
        CP_COMMIT();
    };

    wmma::fragment<wmma::accumulator, 16, 16, 8, float> acc0, acc1;
    wmma::fill_fragment(acc0, 0.f);
    wmma::fill_fragment(acc1, 0.f);

    ISSUE(0);
    ISSUE(1);
    for (int it = 0; it < NIT; ++it) {
        const int stage = it % 3;
        if (it == NIT - 1) asm volatile("cp.async.wait_group 0;");
        else               asm volatile("cp.async.wait_group 1;");
        __syncthreads();
        if (it + 2 < NIT) ISSUE(it + 2);

        const float* A = fA + stage * (32 * 40);
        const float* B = fB + stage * (32 * 100);
#pragma unroll
        for (int ks = 0; ks < 4; ++ks) {
            wmma::fragment<wmma::matrix_a, 16, 16, 8, wmma::precision::tf32, wmma::row_major> a0, a1;
            wmma::fragment<wmma::matrix_b, 16, 16, 8, wmma::precision::tf32, wmma::row_major> bf;
            wmma::load_matrix_sync(a0, A + ks * 8, 40);
            wmma::load_matrix_sync(a1, A + 16 * 40 + ks * 8, 40);
            wmma::load_matrix_sync(bf, B + (ks * 8) * 100 + w * 16, 100);
#pragma unroll
            for (int i = 0; i < a0.num_elements; ++i) {
                a0.x[i] = wmma::__float_to_tf32(a0.x[i]);
                a1.x[i] = wmma::__float_to_tf32(a1.x[i]);
            }
#pragma unroll
            for (int i = 0; i < bf.num_elements; ++i)
                bf.x[i] = wmma::__float_to_tf32(bf.x[i]);
            wmma::mma_sync(acc0, a0, bf, acc0);
            wmma::mma_sync(acc1, a1, bf, acc1);
        }
    }

    __syncthreads();
    float* so = (float*)smc;                   // 32 x 96 staging (reuse stage mem)
    wmma::store_matrix_sync(so + w * 16, acc0, DC, wmma::mem_row_major);
    wmma::store_matrix_sync(so + 16 * DC + w * 16, acc1, DC, wmma::mem_row_major);
    __syncthreads();
#pragma unroll
    for (int j = 0; j < 16; ++j) {
        int idx = tid + j * 192;               // 3072 outputs
        int m = idx / DC, c = idx % DC;
        float inv = 1.f / (g_npts[b * kM + m] + 1e-12f);
        g_avg[(size_t)(b * kM + m) * kD + dc * DC + c] = so[m * DC + c] * inv;
    }
}

// ---------------------------------------------------------------------------
// logits = scale * emb @ avg^T  (512x512x768) via tf32 wmma.
// CTA = 64x64 tile, grid 8x8, 8 warps in 2x4; writes logits AND logits^T.
// ---------------------------------------------------------------------------
constexpr int LK = 32;                          // k per stage
__global__ __launch_bounds__(256) void logits_mma(const float* __restrict__ emb,
                                                  const float* __restrict__ lscale) {
    __shared__ __align__(16) float sA[2][64][36];
    __shared__ __align__(16) float sB[2][64][36];
    const int tid = threadIdx.x, w = tid >> 5;
    const int mw = w >> 2, nw = w & 3;
    const int bi = blockIdx.y, bj = blockIdx.x;
    const uint32_t aA = (uint32_t)__cvta_generic_to_shared(&sA[0][0][0]);
    const uint32_t aB = (uint32_t)__cvta_generic_to_shared(&sB[0][0][0]);

    auto ISSUE = [&](int it) {
        int st = it & 1, k0 = it * LK;
#pragma unroll
        for (int j = 0; j < 2; ++j) {           // 512 chunks each matrix
            int e = tid + j * 256;
            int r = e >> 3, c4 = e & 7;
            cpa16(aA + (uint32_t)((st * 64 + r) * 36 + c4 * 4) * 4,
                  emb + (size_t)(bi * 64 + r) * kD + k0 + c4 * 4);
            cpa16(aB + (uint32_t)((st * 64 + r) * 36 + c4 * 4) * 4,
                  g_avg + (size_t)(bj * 64 + r) * kD + k0 + c4 * 4);
        }
        CP_COMMIT();
    };

    wmma::fragment<wmma::accumulator, 16, 16, 8, float> acc0, acc1;
    wmma::fill_fragment(acc0, 0.f);
    wmma::fill_fragment(acc1, 0.f);

    ISSUE(0);
    const int KIT = kD / LK;                    // 24
    for (int it = 0; it < KIT; ++it) {
        int st = it & 1;
        asm volatile("cp.async.wait_group 0;");
        __syncthreads();
        if (it + 1 < KIT) ISSUE(it + 1);
#pragma unroll
        for (int ks = 0; ks < 4; ++ks) {
            wmma::fragment<wmma::matrix_a, 16, 16, 8, wmma::precision::tf32, wmma::row_major> a0, a1;
            wmma::fragment<wmma::matrix_b, 16, 16, 8, wmma::precision::tf32, wmma::col_major> bf;
            wmma::load_matrix_sync(a0, &sA[st][mw * 32][ks * 8], 36);
            wmma::load_matrix_sync(a1, &sA[st][mw * 32 + 16][ks * 8], 36);
            wmma::load_matrix_sync(bf, &sB[st][nw * 16][ks * 8], 36);
#pragma unroll
            for (int i = 0; i < a0.num_elements; ++i) {
                a0.x[i] = wmma::__float_to_tf32(a0.x[i]);
                a1.x[i] = wmma::__float_to_tf32(a1.x[i]);
            }
#pragma unroll
            for (int i = 0; i < bf.num_elements; ++i)
                bf.x[i] = wmma::__float_to_tf32(bf.x[i]);
            wmma::mma_sync(acc0, a0, bf, acc0);
            wmma::mma_sync(acc1, a1, bf, acc1);
        }
        __syncthreads();
    }

    float* so = &sA[0][0][0];                   // 64 x 68 staging (reuse)
    wmma::store_matrix_sync(so + (mw * 32) * 68 + nw * 16, acc0, 68, wmma::mem_row_major);
    wmma::store_matrix_sync(so + (mw * 32 + 16) * 68 + nw * 16, acc1, 68, wmma::mem_row_major);
    __syncthreads();
    const float scale = expf(lscale[0]);
#pragma unroll
    for (int j = 0; j < 4; ++j) {               // logits rows (coalesced)
        int e = tid + j * 256;
        int r = e >> 4, c4 = e & 15;
        float4 v = *(float4*)(so + r * 68 + c4 * 4);
        v.x *= scale; v.y *= scale; v.z *= scale; v.w *= scale;
        *(float4*)&g_logits[(size_t)(bi * 64 + r) * kN + bj * 64 + c4 * 4] = v;
    }
#pragma unroll
    for (int j = 0; j < 4; ++j) {               // logits^T rows (coalesced)
        int e = tid + j * 256;
        int c = e >> 4, r4 = e & 15;
        float4 v = make_float4(so[(r4 * 4 + 0) * 68 + c], so[(r4 * 4 + 1) * 68 + c],
                               so[(r4 * 4 + 2) * 68 + c], so[(r4 * 4 + 3) * 68 + c]);
        v.x *= scale; v.y *= scale; v.z *= scale; v.w *= scale;
        *(float4*)&g_logitsT[(size_t)(bj * 64 + c) * kN + bi * 64 + r4 * 4] = v;
    }
}

// ---------------------------------------------------------------------------
// Loss: blocks 0..511 do rows of logits (texts_loss); 512..1023 rows of
// logits^T (pts_loss). All reads coalesced.
// ---------------------------------------------------------------------------
__global__ __launch_bounds__(128) void loss_kernel() {
    const int bid = blockIdx.x;
    const int i = bid & (kN - 1);
    const float* __restrict__ row = (bid < kN ? g_logits : g_logitsT) + (size_t)i * kN;
    const int t = threadIdx.x;
    __shared__ float sr[128];

    float rmax = -3.0e38f;
#pragma unroll
    for (int j = t; j < kN; j += 128) rmax = fmaxf(rmax, row[j]);
    sr[t] = rmax;
    __syncthreads();
    for (int w = 64; w > 0; w >>= 1) {
        if (t < w) sr[t] = fmaxf(sr[t], sr[t + w]);
        __syncthreads();
    }
    rmax = sr[0];
    __syncthreads();

    float rs = 0.f;
#pragma unroll
    for (int j = t; j < kN; j += 128) rs += expf(row[j] - rmax);
    sr[t] = rs;
    __syncthreads();
    for (int w = 64; w > 0; w >>= 1) {
        if (t < w) sr[t] += sr[t + w];
        __syncthreads();
    }
    if (t == 0) {
        bool valid = g_npts[i] > 0.f;
        float lse = rmax + logf(sr[0]) - row[i];
        (bid < kN ? g_tloss : g_ploss)[i] = valid ? lse : 0.f;
    }
}

// ---------------------------------------------------------------------------
// Final: nonzero-mean of both loss vectors, averaged.
// ---------------------------------------------------------------------------
__global__ void final_kernel(float* __restrict__ out) {
    const int t = threadIdx.x;   // 512 threads
    __shared__ float s_ts[512], s_tc[512], s_ps[512], s_pc[512];
    float tl = g_tloss[t], pl = g_ploss[t];
    s_ts[t] = (tl > 0.f) ? tl : 0.f;
    s_tc[t] = (tl > 0.f) ? 1.f : 0.f;
    s_ps[t] = (pl > 0.f) ? pl : 0.f;
    s_pc[t] = (pl > 0.f) ? 1.f : 0.f;
    __syncthreads();
    for (int w = 256; w > 0; w >>= 1) {
        if (t < w) {
            s_ts[t] += s_ts[t + w]; s_tc[t] += s_tc[t + w];
            s_ps[t] += s_ps[t + w]; s_pc[t] += s_pc[t + w];
        }
        __syncthreads();
    }
    if (t == 0) {
        float tm = (s_tc[0] > 0.f) ? s_ts[0] / s_tc[0] : 0.f;
        float pm = (s_pc[0] > 0.f) ? s_ps[0] / s_pc[0] : 0.f;
        out[0] = 0.5f * (tm + pm);
    }
}

// ---------------------------------------------------------------------------
// Launch. Inputs: net_out, pt_offset, mask_embs, mask_pts, logit_scale.
// pt_offset encodes the regular b*P layout (fixed shapes) -> not read.
// ---------------------------------------------------------------------------
extern "C" void kernel_launch(void* const* d_in, const int* in_sizes, int n_in,
                              void* d_out, int out_size) {
    (void)in_sizes; (void)n_in; (void)out_size;
    const float* net_out   = (const float*)d_in[0];
    const float* mask_embs = (const float*)d_in[2];
    const float* mask_pts  = (const float*)d_in[3];
    const float* lscale    = (const float*)d_in[4];

    cudaFuncSetAttribute(segsum_mma,
                         cudaFuncAttributeMaxDynamicSharedMemorySize, SEG_SMEM);

    zero_kernel<<<1, kN>>>();
    pack_kernel<<<dim3(kP / 256, kB), 256>>>(mask_pts);
    segsum_mma<<<dim3(NDCC, kB), 192, SEG_SMEM>>>(net_out);
    logits_mma<<<dim3(8, 8), 256>>>(mask_embs, lscale);
    loss_kernel<<<2 * kN, 128>>>();
    final_kernel<<<1, kN>>>((float*)d_out);
}

// round 6
// speedup vs baseline: 2.4462x; 1.5135x over previous
#include <cuda_runtime.h>
#include <mma.h>
#include <math.h>
#include <stdint.h>

using namespace nvcuda;

// Shapes fixed by the problem instance.
constexpr int kB  = 16;            // objects
constexpr int kP  = 4096;          // points per object
constexpr int kM  = 32;            // masks per object
constexpr int kD  = 768;           // feature dim
constexpr int kN  = kB * kM;       // 512 total masks

// Segsum tiling: CTA = (96 d-cols, object), 12 warps, K-tile = 64 points
// split across 2 warp k-groups. Grid 8x16 = 128 CTAs.
constexpr int DC   = 96;
constexpr int NDCC = kD / DC;      // 8
constexpr int KT   = 64;
constexpr int NIT  = kP / KT;      // 64
constexpr int SEG_THREADS = 384;

// Segsum dynamic smem layout (floats / bytes):
constexpr int BST   = 100;                       // B row stride (floats)
constexpr int B_STG = KT * BST * 4;              // 25600 B per stage
constexpr int AST   = 72;                        // A row stride (floats)
constexpr int A_OFF = 3 * B_STG;                 // 76800
constexpr int A_STG = kM * AST * 4;              // 9216 B per stage
constexpr int SEG_SMEM = A_OFF + 3 * A_STG;      // 104448 B

// Scratch (device globals; no allocation allowed).
__device__ float g_afloat[kB * kM * kP];   // mask as fp32 {0,1}, [b][m][p] (8 MB)
__device__ float g_npts[kN];
__device__ float g_avg[kN * kD];
__device__ float g_logits[kN * kN];
__device__ float g_logitsT[kN * kN];
__device__ float g_tloss[kN];
__device__ float g_ploss[kN];

__device__ __forceinline__ void cpa16(uint32_t dst, const void* src) {
    asm volatile("cp.async.ca.shared.global [%0], [%1], 16;" :: "r"(dst), "l"(src));
}
#define CP_COMMIT() asm volatile("cp.async.commit_group;")

// ---------------------------------------------------------------------------
__global__ void zero_kernel() { g_npts[threadIdx.x] = 0.f; }

// ---------------------------------------------------------------------------
// Pack: mask_pts [b][m][p] -> g_afloat (fp32 0/1) + npts (ballot popc, exact).
// ---------------------------------------------------------------------------
__global__ void pack_kernel(const float* __restrict__ mp) {
    const int b = blockIdx.y;
    const int p = blockIdx.x * blockDim.x + threadIdx.x;
    const int lane = threadIdx.x & 31;
    unsigned bm = 0;
#pragma unroll
    for (int m = 0; m < kM; ++m) {
        size_t idx = ((size_t)(b * kM + m)) * kP + p;
        float v = mp[idx];
        bool on = v > 0.5f;
        bm |= on ? (1u << m) : 0u;
        g_afloat[idx] = on ? 1.f : 0.f;
    }
    unsigned cmine = 0;
#pragma unroll
    for (int m = 0; m < kM; ++m) {
        unsigned bal = __ballot_sync(0xffffffffu, (bm >> m) & 1u);
        if (lane == m) cmine = __popc(bal);
    }
    atomicAdd(&g_npts[b * kM + lane], (float)cmine);
}

// ---------------------------------------------------------------------------
// Segmented sum via tf32 wmma; avg fused into epilogue.
// Per CTA (dc, b): out[32, 96] = mask[32, 4096] @ net_out_b[4096, 96]
// 12 warps: kg = w & 1 (k-half of the 64-pt tile), nw = w >> 1 (16-col group).
// 3-stage cp.async pipeline; A tile is pure cp.async from g_afloat.
// ---------------------------------------------------------------------------
__global__ __launch_bounds__(SEG_THREADS) void segsum_mma(const float* __restrict__ net_out) {
    extern __shared__ char smc[];
    float* smB = (float*)smc;
    float* smA = (float*)(smc + A_OFF);
    const uint32_t base = (uint32_t)__cvta_generic_to_shared(smc);
    const int tid = threadIdx.x, w = tid >> 5;
    const int kg = w & 1, nw = w >> 1;
    const int dc = blockIdx.x, b = blockIdx.y;
    const float4* __restrict__ net4 =
        (const float4*)net_out + (size_t)b * kP * (kD / 4) + dc * (DC / 4);
    const float* __restrict__ afl = g_afloat + (size_t)b * kM * kP;

    auto ISSUE = [&](int it) {
        const int stage = it % 3;
        const int p0 = it * KT;
        const uint32_t bb = base + stage * B_STG;
        const uint32_t ab = base + A_OFF + stage * A_STG;
#pragma unroll
        for (int j = 0; j < 4; ++j) {                  // B: 64 rows x 24 chunks
            int c = tid + j * SEG_THREADS;
            int r = c / 24, c16 = c % 24;
            cpa16(bb + (uint32_t)(r * BST + c16 * 4) * 4,
                  net4 + (size_t)(p0 + r) * (kD / 4) + c16);
        }
        for (int c = tid; c < 512; c += SEG_THREADS) { // A: 32 rows x 16 chunks
            int r = c >> 4, c16 = c & 15;
            cpa16(ab + (uint32_t)(r * AST + c16 * 4) * 4,
                  afl + (size_t)r * kP + p0 + c16 * 4);
        }
        CP_COMMIT();
    };

    wmma::fragment<wmma::accumulator, 16, 16, 8, float> acc0, acc1;
    wmma::fill_fragment(acc0, 0.f);
    wmma::fill_fragment(acc1, 0.f);

    ISSUE(0);
    ISSUE(1);
    for (int it = 0; it < NIT; ++it) {
        const int stage = it % 3;
        if (it == NIT - 1) asm volatile("cp.async.wait_group 0;");
        else               asm volatile("cp.async.wait_group 1;");
        __syncthreads();
        if (it + 2 < NIT) ISSUE(it + 2);

        const float* A = smA + stage * (A_STG / 4);
        const float* B = smB + stage * (B_STG / 4);
#pragma unroll
        for (int ks = 0; ks < 4; ++ks) {
            const int kk = kg * 32 + ks * 8;
            wmma::fragment<wmma::matrix_a, 16, 16, 8, wmma::precision::tf32, wmma::row_major> a0, a1;
            wmma::fragment<wmma::matrix_b, 16, 16, 8, wmma::precision::tf32, wmma::row_major> bf;
            wmma::load_matrix_sync(a0, A + kk, AST);
            wmma::load_matrix_sync(a1, A + 16 * AST + kk, AST);
            wmma::load_matrix_sync(bf, B + kk * BST + nw * 16, BST);
            // A is exact {0,1} in tf32; round only B.
#pragma unroll
            for (int i = 0; i < bf.num_elements; ++i)
                bf.x[i] = wmma::__float_to_tf32(bf.x[i]);
            wmma::mma_sync(acc0, a0, bf, acc0);
            wmma::mma_sync(acc1, a1, bf, acc1);
        }
    }

    // Reduce kg halves + fused avg. Reuse smB as staging: [2][32][96].
    __syncthreads();
    float* so = smB + kg * (kM * DC);
    wmma::store_matrix_sync(so + nw * 16, acc0, DC, wmma::mem_row_major);
    wmma::store_matrix_sync(so + 16 * DC + nw * 16, acc1, DC, wmma::mem_row_major);
    __syncthreads();
#pragma unroll
    for (int j = 0; j < 8; ++j) {
        int idx = tid + j * SEG_THREADS;               // 3072 outputs
        int m = idx / DC, c = idx % DC;
        float v = smB[idx] + smB[kM * DC + idx];
        float inv = 1.f / (g_npts[b * kM + m] + 1e-12f);
        g_avg[(size_t)(b * kM + m) * kD + dc * DC + c] = v * inv;
    }
}

// ---------------------------------------------------------------------------
// logits = scale * emb @ avg^T  (512x512x768) via tf32 wmma.
// CTA = 32x64 tile, grid (8, 16) = 128 CTAs; 8 warps 2x4; 3-stage cp.async.
// Writes logits AND logits^T (coalesced loss passes).
// ---------------------------------------------------------------------------
constexpr int LK = 32;
__global__ __launch_bounds__(256) void logits_mma(const float* __restrict__ emb,
                                                  const float* __restrict__ lscale) {
    __shared__ __align__(16) float sA[3][32][36];
    __shared__ __align__(16) float sB[3][64][36];
    const int tid = threadIdx.x, w = tid >> 5;
    const int mw = w >> 2, nw = w & 3;
    const int bi = blockIdx.y, bj = blockIdx.x;
    const uint32_t aA = (uint32_t)__cvta_generic_to_shared(&sA[0][0][0]);
    const uint32_t aB = (uint32_t)__cvta_generic_to_shared(&sB[0][0][0]);

    auto ISSUE = [&](int it) {
        int st = it % 3, k0 = it * LK;
        if (tid < 256) {                        // A: 32 rows x 8 chunks
            int r = tid >> 3, c4 = tid & 7;
            cpa16(aA + (uint32_t)(st * 32 * 36 + r * 36 + c4 * 4) * 4,
                  emb + (size_t)(bi * 32 + r) * kD + k0 + c4 * 4);
        }
#pragma unroll
        for (int j = 0; j < 2; ++j) {           // B: 64 rows x 8 chunks
            int e = tid + j * 256;
            int r = e >> 3, c4 = e & 7;
            cpa16(aB + (uint32_t)(st * 64 * 36 + r * 36 + c4 * 4) * 4,
                  g_avg + (size_t)(bj * 64 + r) * kD + k0 + c4 * 4);
        }
        CP_COMMIT();
    };

    wmma::fragment<wmma::accumulator, 16, 16, 8, float> acc;
    wmma::fill_fragment(acc, 0.f);

    ISSUE(0);
    ISSUE(1);
    const int KIT = kD / LK;                    // 24
    for (int it = 0; it < KIT; ++it) {
        int st = it % 3;
        if (it == KIT - 1) asm volatile("cp.async.wait_group 0;");
        else               asm volatile("cp.async.wait_group 1;");
        __syncthreads();
        if (it + 2 < KIT) ISSUE(it + 2);
#pragma unroll
        for (int ks = 0; ks < 4; ++ks) {
            wmma::fragment<wmma::matrix_a, 16, 16, 8, wmma::precision::tf32, wmma::row_major> af;
            wmma::fragment<wmma::matrix_b, 16, 16, 8, wmma::precision::tf32, wmma::col_major> bf;
            wmma::load_matrix_sync(af, &sA[st][mw * 16][ks * 8], 36);
            wmma::load_matrix_sync(bf, &sB[st][nw * 16][ks * 8], 36);
#pragma unroll
            for (int i = 0; i < af.num_elements; ++i)
                af.x[i] = wmma::__float_to_tf32(af.x[i]);
#pragma unroll
            for (int i = 0; i < bf.num_elements; ++i)
                bf.x[i] = wmma::__float_to_tf32(bf.x[i]);
            wmma::mma_sync(acc, af, bf, acc);
        }
        __syncthreads();
    }

    float* so = &sA[0][0][0];                   // 32 x 68 staging (reuse)
    wmma::store_matrix_sync(so + (mw * 16) * 68 + nw * 16, acc, 68, wmma::mem_row_major);
    __syncthreads();
    const float scale = expf(lscale[0]);
#pragma unroll
    for (int j = 0; j < 2; ++j) {               // logits rows (coalesced)
        int e = tid + j * 256;                  // 512 float4 chunks
        int r = e >> 4, c4 = e & 15;
        float4 v = *(float4*)(so + r * 68 + c4 * 4);
        v.x *= scale; v.y *= scale; v.z *= scale; v.w *= scale;
        *(float4*)&g_logits[(size_t)(bi * 32 + r) * kN + bj * 64 + c4 * 4] = v;
    }
#pragma unroll
    for (int j = 0; j < 2; ++j) {               // logits^T rows (coalesced)
        int e = tid + j * 256;
        int c = e & 63, i4 = e >> 6;            // col of logits, row-quad of i
        float4 v = make_float4(so[(i4 * 4 + 0) * 68 + c] * scale,
                               so[(i4 * 4 + 1) * 68 + c] * scale,
                               so[(i4 * 4 + 2) * 68 + c] * scale,
                               so[(i4 * 4 + 3) * 68 + c] * scale);
        *(float4*)&g_logitsT[(size_t)(bj * 64 + c) * kN + bi * 32 + i4 * 4] = v;
    }
}

// ---------------------------------------------------------------------------
// Loss: blocks 0..511 rows of logits (texts); 512..1023 rows of logits^T (pts).
// ---------------------------------------------------------------------------
__global__ __launch_bounds__(128) void loss_kernel() {
    const int bid = blockIdx.x;
    const int i = bid & (kN - 1);
    const float* __restrict__ row = (bid < kN ? g_logits : g_logitsT) + (size_t)i * kN;
    const int t = threadIdx.x;
    __shared__ float sr[128];

    float rmax = -3.0e38f;
#pragma unroll
    for (int j = t; j < kN; j += 128) rmax = fmaxf(rmax, row[j]);
    sr[t] = rmax;
    __syncthreads();
    for (int w = 64; w > 0; w >>= 1) {
        if (t < w) sr[t] = fmaxf(sr[t], sr[t + w]);
        __syncthreads();
    }
    rmax = sr[0];
    __syncthreads();

    float rs = 0.f;
#pragma unroll
    for (int j = t; j < kN; j += 128) rs += expf(row[j] - rmax);
    sr[t] = rs;
    __syncthreads();
    for (int w = 64; w > 0; w >>= 1) {
        if (t < w) sr[t] += sr[t + w];
        __syncthreads();
    }
    if (t == 0) {
        bool valid = g_npts[i] > 0.f;
        float lse = rmax + logf(sr[0]) - row[i];
        (bid < kN ? g_tloss : g_ploss)[i] = valid ? lse : 0.f;
    }
}

// ---------------------------------------------------------------------------
// Final: nonzero-mean of both loss vectors, averaged.
// ---------------------------------------------------------------------------
__global__ void final_kernel(float* __restrict__ out) {
    const int t = threadIdx.x;   // 512 threads
    __shared__ float s_ts[512], s_tc[512], s_ps[512], s_pc[512];
    float tl = g_tloss[t], pl = g_ploss[t];
    s_ts[t] = (tl > 0.f) ? tl : 0.f;
    s_tc[t] = (tl > 0.f) ? 1.f : 0.f;
    s_ps[t] = (pl > 0.f) ? pl : 0.f;
    s_pc[t] = (pl > 0.f) ? 1.f : 0.f;
    __syncthreads();
    for (int w = 256; w > 0; w >>= 1) {
        if (t < w) {
            s_ts[t] += s_ts[t + w]; s_tc[t] += s_tc[t + w];
            s_ps[t] += s_ps[t + w]; s_pc[t] += s_pc[t + w];
        }
        __syncthreads();
    }
    if (t == 0) {
        float tm = (s_tc[0] > 0.f) ? s_ts[0] / s_tc[0] : 0.f;
        float pm = (s_pc[0] > 0.f) ? s_ps[0] / s_pc[0] : 0.f;
        out[0] = 0.5f * (tm + pm);
    }
}

// ---------------------------------------------------------------------------
// Launch. Inputs: net_out, pt_offset, mask_embs, mask_pts, logit_scale.
// ---------------------------------------------------------------------------
extern "C" void kernel_launch(void* const* d_in, const int* in_sizes, int n_in,
                              void* d_out, int out_size) {
    (void)in_sizes; (void)n_in; (void)out_size;
    const float* net_out   = (const float*)d_in[0];
    const float* mask_embs = (const float*)d_in[2];
    const float* mask_pts  = (const float*)d_in[3];
    const float* lscale    = (const float*)d_in[4];

    cudaFuncSetAttribute(segsum_mma,
                         cudaFuncAttributeMaxDynamicSharedMemorySize, SEG_SMEM);

    zero_kernel<<<1, kN>>>();
    pack_kernel<<<dim3(kP / 256, kB), 256>>>(mask_pts);
    segsum_mma<<<dim3(NDCC, kB), SEG_THREADS, SEG_SMEM>>>(net_out);
    logits_mma<<<dim3(8, 16), 256>>>(mask_embs, lscale);
    loss_kernel<<<2 * kN, 128>>>();
    final_kernel<<<1, kN>>>((float*)d_out);
}